// round 5
// baseline (speedup 1.0000x reference)
#include <cuda_runtime.h>
#include <cuda_bf16.h>
#include <cstdint>

// ---------------------------------------------------------------------------
// YOLO loss (nc=1).  B=64, N=32, A=3, grids {160,80,40}, pred [B,18,G,G].
//
// loss = 0.05 * sum_s box_sq[s]/n_pos[s]
//      +        sum_s ( pos_plus[s]/n_pos[s] + (S_all[s]-pos_neg[s])/n_neg[s] )
//
// Kernel 1 (1284 blocks): NO global atomics anywhere.
//   blocks [0,24):       192 warp-tasks (scale,batch) -> g_tpart[task] (float4)
//   blocks [24,1284):    dense objectness softplus sums -> g_part[block]
// Kernel 2 (1 block):    reduce partials, compute loss, write out.
// All device state is fully overwritten each replay -> no reset needed.
// ---------------------------------------------------------------------------

#define NN 32
#define NB0 960                  // scale0: 1228800 f4 / 1280
#define NB1 240                  // scale1:  307200 f4 / 1280
#define NB2 60                   // scale2:   76800 f4 / 1280
#define TGT_BLOCKS 24
#define DENSE_BLOCKS (NB0 + NB1 + NB2)            // 1260
#define TOTAL_BLOCKS (TGT_BLOCKS + DENSE_BLOCKS)  // 1284

__device__ double g_part[DENSE_BLOCKS];   // dense per-block partials
__device__ float4 g_tpart[192];           // target per-warp partials: sq, sp-, sp+, cnt

__device__ __forceinline__ float sp(float x) {
    return fmaxf(x, 0.0f) + __logf(1.0f + __expf(-fabsf(x)));
}

// gathered obj-channel index -> physical float4 index:
//   idx = p*HW4 + pos, plane p -> channel 6p+4  =>  phys = 6*idx + 4*HW4 - 5*pos
template <int HW4>
__device__ __forceinline__ const float4* obj_ptr(const float4* __restrict__ p4, int idx) {
    int pos = idx - (idx / HW4) * HW4;
    return p4 + (size_t)(6 * idx + 4 * HW4 - 5 * pos);
}

template <int HW4>
__device__ __forceinline__ float dense_sum(const float* __restrict__ pred,
                                           int localb, int tid) {
    const float4* p4 = reinterpret_cast<const float4*>(pred);
    const int base = localb * 1280 + tid;

    float4 v0 = __ldg(obj_ptr<HW4>(p4, base));
    float4 v1 = __ldg(obj_ptr<HW4>(p4, base + 256));
    float4 v2 = __ldg(obj_ptr<HW4>(p4, base + 512));
    float4 v3 = __ldg(obj_ptr<HW4>(p4, base + 768));
    float4 v4 = __ldg(obj_ptr<HW4>(p4, base + 1024));

    float alin = 0.0f, alog = 0.0f;
    float4 vv[5] = {v0, v1, v2, v3, v4};
    #pragma unroll
    for (int k = 0; k < 5; k++) {
        const float xs[4] = {vv[k].x, vv[k].y, vv[k].z, vv[k].w};
        #pragma unroll
        for (int e = 0; e < 4; e++) {
            float x = xs[e];
            alin += fmaxf(x, 0.0f);
            alog += __log2f(1.0f + __expf(-fabsf(x)));
        }
    }
    return alin + 0.69314718055994531f * alog;
}

__global__ void yolo_main_kernel(
        const float* __restrict__ pred0,
        const float* __restrict__ pred1,
        const float* __restrict__ pred2,
        const float* __restrict__ boxes,
        const float* __restrict__ anchors) {
    const int bid  = blockIdx.x;
    const int tid  = threadIdx.x;
    const int lane = tid & 31;
    const int wid  = tid >> 5;

    if (bid >= TGT_BLOCKS) {
        // ---------------- dense objectness pass ----------------
        __shared__ float warpsum[8];
        const int d = bid - TGT_BLOCKS;
        float v;
        if (d < NB0)            v = dense_sum<6400>(pred0, d, tid);
        else if (d < NB0 + NB1) v = dense_sum<1600>(pred1, d - NB0, tid);
        else                    v = dense_sum< 400>(pred2, d - NB0 - NB1, tid);

        #pragma unroll
        for (int o = 16; o > 0; o >>= 1)
            v += __shfl_down_sync(0xffffffffu, v, o);
        if (lane == 0) warpsum[wid] = v;
        __syncthreads();
        if (tid == 0) {
            double t = 0.0;
            #pragma unroll
            for (int w = 0; w < 8; w++) t += (double)warpsum[w];
            g_part[d] = t;
        }
    } else {
        // ---------------- sparse target pass: one (scale,batch) per warp ----------------
        __shared__ int keys[8][NN];
        const int task = bid * 8 + wid;          // 0..191
        const int s = task >> 6;
        const int b = task & 63;
        const int n = lane;

        const int G = (s == 0) ? 160 : (s == 1) ? 80 : 40;
        const float* pred = (s == 0) ? pred0 : (s == 1) ? pred1 : pred2;
        const int HW = G * G;

        float4 bx = reinterpret_cast<const float4*>(boxes)[b * NN + n];
        float gx = bx.x * (float)G;
        float gy = bx.y * (float)G;
        float gw = bx.z * (float)G;
        float gh = bx.w * (float)G;
        int gi = (int)gx;
        int gj = (int)gy;

        // anchor matching: argmax over a of prod(min(r,1/r)), first-max tiebreak
        float bestIou = -1.0f;
        float aw = 1.0f, ah = 1.0f;
        int best = 0;
        #pragma unroll
        for (int a = 0; a < 3; a++) {
            float Aw = anchors[s * 6 + a * 2 + 0];
            float Ah = anchors[s * 6 + a * 2 + 1];
            float rw = __fdiv_rn(Aw, gw);
            float rh = __fdiv_rn(Ah, gh);
            float iw = fminf(rw, __fdiv_rn(1.0f, rw));
            float ih = fminf(rh, __fdiv_rn(1.0f, rh));
            float iou = iw * ih;
            if (iou > bestIou) { bestIou = iou; best = a; aw = Aw; ah = Ah; }
        }

        // dedup: last write wins -> entry n live iff no later n' has same key
        int key = (best * G + gj) * G + gi;
        keys[wid][n] = key;
        __syncwarp();
        bool live = true;
        for (int m = n + 1; m < NN; m++)
            if (keys[wid][m] == key) { live = false; break; }

        float sq = 0.0f, spp = 0.0f, spm = 0.0f, cnt = 0.0f;
        if (live) {
            size_t base = (size_t)(b * 18 + best * 6) * HW + (size_t)gj * G + gi;
            float p0 = __ldg(pred + base);
            float p1 = __ldg(pred + base + (size_t)HW);
            float p2 = __ldg(pred + base + (size_t)2 * HW);
            float p3 = __ldg(pred + base + (size_t)3 * HW);
            float p4 = __ldg(pred + base + (size_t)4 * HW);

            float tx = gx - (float)gi;
            float ty = gy - (float)gj;
            float tw = logf(__fdiv_rn(gw, aw) + 1e-16f);
            float th = logf(__fdiv_rn(gh, ah) + 1e-16f);

            float d0 = p0 - tx, d1 = p1 - ty, d2 = p2 - tw, d3 = p3 - th;
            sq  = d0 * d0 + d1 * d1 + d2 * d2 + d3 * d3;
            spm = sp(-p4);
            spp = sp(p4);
            cnt = 1.0f;
        }

        #pragma unroll
        for (int o = 16; o > 0; o >>= 1) {
            sq  += __shfl_down_sync(0xffffffffu, sq,  o);
            spm += __shfl_down_sync(0xffffffffu, spm, o);
            spp += __shfl_down_sync(0xffffffffu, spp, o);
            cnt += __shfl_down_sync(0xffffffffu, cnt, o);
        }
        if (n == 0)
            g_tpart[task] = make_float4(sq, spm, spp, cnt);
    }
}

__global__ void yolo_finalize_kernel(float* __restrict__ out) {
    const int tid  = threadIdx.x;
    const int lane = tid & 31;
    const int wid  = tid >> 5;

    __shared__ double dsh[3][8];
    __shared__ double tsh[4][6];   // sq, spm, spp, cnt  per warp (warps 0..5)

    // ---- dense partials: per-scale sums ----
    double v0 = 0.0, v1 = 0.0, v2 = 0.0;
    for (int i = tid; i < NB0; i += 256) v0 += g_part[i];
    if (tid < NB1) v1 = g_part[NB0 + tid];
    if (tid < NB2) v2 = g_part[NB0 + NB1 + tid];
    #pragma unroll
    for (int o = 16; o > 0; o >>= 1) {
        v0 += __shfl_down_sync(0xffffffffu, v0, o);
        v1 += __shfl_down_sync(0xffffffffu, v1, o);
        v2 += __shfl_down_sync(0xffffffffu, v2, o);
    }
    if (lane == 0) { dsh[0][wid] = v0; dsh[1][wid] = v1; dsh[2][wid] = v2; }

    // ---- target partials: warps 0..5, warp w handles tasks [w*32, w*32+32) ----
    if (wid < 6) {
        float4 tp = g_tpart[wid * 32 + lane];
        double a = tp.x, b = tp.y, c = tp.z, d = tp.w;
        #pragma unroll
        for (int o = 16; o > 0; o >>= 1) {
            a += __shfl_down_sync(0xffffffffu, a, o);
            b += __shfl_down_sync(0xffffffffu, b, o);
            c += __shfl_down_sync(0xffffffffu, c, o);
            d += __shfl_down_sync(0xffffffffu, d, o);
        }
        if (lane == 0) { tsh[0][wid] = a; tsh[1][wid] = b; tsh[2][wid] = c; tsh[3][wid] = d; }
    }
    __syncthreads();

    if (tid == 0) {
        double sall[3];
        #pragma unroll
        for (int s = 0; s < 3; s++) {
            double t = 0.0;
            #pragma unroll
            for (int w = 0; w < 8; w++) t += dsh[s][w];
            sall[s] = t;
        }
        const double cells[3] = {4915200.0, 1228800.0, 307200.0}; // B*A*H*W
        double loss = 0.0;
        #pragma unroll
        for (int s = 0; s < 3; s++) {
            // tasks for scale s -> warps 2s, 2s+1
            double box = tsh[0][2 * s] + tsh[0][2 * s + 1];
            double pp  = tsh[1][2 * s] + tsh[1][2 * s + 1];
            double pn  = tsh[2][2 * s] + tsh[2][2 * s + 1];
            double np  = tsh[3][2 * s] + tsh[3][2 * s + 1];
            double nn  = cells[s] - np;
            loss += 0.05 * box / np + pp / np + (sall[s] - pn) / nn;
        }
        out[0] = (float)loss;
    }
}

extern "C" void kernel_launch(void* const* d_in, const int* in_sizes, int n_in,
                              void* d_out, int out_size) {
    (void)in_sizes; (void)n_in; (void)out_size;
    const float* pred0   = (const float*)d_in[0];
    const float* pred1   = (const float*)d_in[1];
    const float* pred2   = (const float*)d_in[2];
    const float* boxes   = (const float*)d_in[3];
    // d_in[4] = labels (unused, nc==1)
    const float* anchors = (const float*)d_in[5];
    float* out = (float*)d_out;

    yolo_main_kernel<<<TOTAL_BLOCKS, 256>>>(pred0, pred1, pred2, boxes, anchors);
    yolo_finalize_kernel<<<1, 256>>>(out);
}

// round 6
// speedup vs baseline: 1.0530x; 1.0530x over previous
#include <cuda_runtime.h>
#include <cuda_bf16.h>
#include <cstdint>

// ---------------------------------------------------------------------------
// YOLO loss (nc=1).  B=64, N=32, A=3, grids {160,80,40}, pred [B,18,G,G].
//
// loss = 0.05 * sum_s box_sq[s]/n_pos[s]
//      +        sum_s ( pos_plus[s]/n_pos[s] + (S_all[s]-pos_neg[s])/n_neg[s] )
//
// Kernel 1 (654 blocks, __launch_bounds__(256,2) so ptxas keeps 10 LDG.128
//           per thread IN FLIGHT — regs~70, MLP=10):
//   blocks [0,24):     192 warp-tasks (scale,batch) -> g_tpart[task]
//   blocks [24,654):   dense objectness softplus sums -> g_part[block]
// Kernel 2 (1 block):  reduce partials, compute loss, write out.
// ---------------------------------------------------------------------------

#define NN 32
#define NB0 480                  // scale0: 1228800 f4 / 2560
#define NB1 120                  // scale1:  307200 f4 / 2560
#define NB2 30                   // scale2:   76800 f4 / 2560
#define TGT_BLOCKS 24
#define DENSE_BLOCKS (NB0 + NB1 + NB2)            // 630
#define TOTAL_BLOCKS (TGT_BLOCKS + DENSE_BLOCKS)  // 654

__device__ double g_part[DENSE_BLOCKS];   // dense per-block partials
__device__ float4 g_tpart[192];           // target partials: sq, sp-, sp+, cnt

__device__ __forceinline__ float sp(float x) {
    return fmaxf(x, 0.0f) + __logf(1.0f + __expf(-fabsf(x)));
}

// 10 front-batched independent float4 loads per thread, then compute.
template <int HW4>
__device__ __forceinline__ float dense_sum(const float* __restrict__ pred,
                                           int localb, int tid) {
    const float4* p4 = reinterpret_cast<const float4*>(pred);
    const int base = localb * 2560 + tid;

    // compute all 10 addresses first (independent), then all 10 loads
    const float4* ptr[10];
    #pragma unroll
    for (int k = 0; k < 10; k++) {
        int idx = base + k * 256;
        int p   = idx / HW4;               // obj plane index (b*3 + a)
        int pos = idx - p * HW4;
        ptr[k] = p4 + (size_t)(p * 6 + 4) * HW4 + pos;
    }
    float4 v[10];
    #pragma unroll
    for (int k = 0; k < 10; k++)
        v[k] = __ldg(ptr[k]);

    // softplus(x) = max(x,0) + ln2 * log2(1 + exp(-|x|)); split accumulators
    float alin = 0.0f, alog = 0.0f;
    #pragma unroll
    for (int k = 0; k < 10; k++) {
        const float xs[4] = {v[k].x, v[k].y, v[k].z, v[k].w};
        #pragma unroll
        for (int e = 0; e < 4; e++) {
            float x = xs[e];
            alin += fmaxf(x, 0.0f);
            alog += __log2f(1.0f + __expf(-fabsf(x)));
        }
    }
    return alin + 0.69314718055994531f * alog;
}

__global__ void __launch_bounds__(256, 2) yolo_main_kernel(
        const float* __restrict__ pred0,
        const float* __restrict__ pred1,
        const float* __restrict__ pred2,
        const float* __restrict__ boxes,
        const float* __restrict__ anchors) {
    const int bid  = blockIdx.x;
    const int tid  = threadIdx.x;
    const int lane = tid & 31;
    const int wid  = tid >> 5;

    if (bid >= TGT_BLOCKS) {
        // ---------------- dense objectness pass ----------------
        __shared__ float warpsum[8];
        const int d = bid - TGT_BLOCKS;
        float v;
        if (d < NB0)            v = dense_sum<6400>(pred0, d, tid);
        else if (d < NB0 + NB1) v = dense_sum<1600>(pred1, d - NB0, tid);
        else                    v = dense_sum< 400>(pred2, d - NB0 - NB1, tid);

        #pragma unroll
        for (int o = 16; o > 0; o >>= 1)
            v += __shfl_down_sync(0xffffffffu, v, o);
        if (lane == 0) warpsum[wid] = v;
        __syncthreads();
        if (tid == 0) {
            double t = 0.0;
            #pragma unroll
            for (int w = 0; w < 8; w++) t += (double)warpsum[w];
            g_part[d] = t;
        }
    } else {
        // ---------------- sparse target pass: one (scale,batch) per warp ----------------
        __shared__ int keys[8][NN];
        const int task = bid * 8 + wid;          // 0..191
        const int s = task >> 6;
        const int b = task & 63;
        const int n = lane;

        const int G = (s == 0) ? 160 : (s == 1) ? 80 : 40;
        const float* pred = (s == 0) ? pred0 : (s == 1) ? pred1 : pred2;
        const int HW = G * G;

        float4 bx = reinterpret_cast<const float4*>(boxes)[b * NN + n];
        float gx = bx.x * (float)G;
        float gy = bx.y * (float)G;
        float gw = bx.z * (float)G;
        float gh = bx.w * (float)G;
        int gi = (int)gx;
        int gj = (int)gy;

        // anchor matching: argmax over a of prod(min(r,1/r)), first-max tiebreak
        float bestIou = -1.0f;
        float aw = 1.0f, ah = 1.0f;
        int best = 0;
        #pragma unroll
        for (int a = 0; a < 3; a++) {
            float Aw = anchors[s * 6 + a * 2 + 0];
            float Ah = anchors[s * 6 + a * 2 + 1];
            float rw = __fdiv_rn(Aw, gw);
            float rh = __fdiv_rn(Ah, gh);
            float iw = fminf(rw, __fdiv_rn(1.0f, rw));
            float ih = fminf(rh, __fdiv_rn(1.0f, rh));
            float iou = iw * ih;
            if (iou > bestIou) { bestIou = iou; best = a; aw = Aw; ah = Ah; }
        }

        // dedup: last write wins -> entry n live iff no later n' has same key
        int key = (best * G + gj) * G + gi;
        keys[wid][n] = key;
        __syncwarp();
        bool live = true;
        for (int m = n + 1; m < NN; m++)
            if (keys[wid][m] == key) { live = false; break; }

        float sq = 0.0f, spp = 0.0f, spm = 0.0f, cnt = 0.0f;
        if (live) {
            size_t base = (size_t)(b * 18 + best * 6) * HW + (size_t)gj * G + gi;
            float p0 = __ldg(pred + base);
            float p1 = __ldg(pred + base + (size_t)HW);
            float p2 = __ldg(pred + base + (size_t)2 * HW);
            float p3 = __ldg(pred + base + (size_t)3 * HW);
            float p4 = __ldg(pred + base + (size_t)4 * HW);

            float tx = gx - (float)gi;
            float ty = gy - (float)gj;
            float tw = logf(__fdiv_rn(gw, aw) + 1e-16f);
            float th = logf(__fdiv_rn(gh, ah) + 1e-16f);

            float d0 = p0 - tx, d1 = p1 - ty, d2 = p2 - tw, d3 = p3 - th;
            sq  = d0 * d0 + d1 * d1 + d2 * d2 + d3 * d3;
            spm = sp(-p4);
            spp = sp(p4);
            cnt = 1.0f;
        }

        #pragma unroll
        for (int o = 16; o > 0; o >>= 1) {
            sq  += __shfl_down_sync(0xffffffffu, sq,  o);
            spm += __shfl_down_sync(0xffffffffu, spm, o);
            spp += __shfl_down_sync(0xffffffffu, spp, o);
            cnt += __shfl_down_sync(0xffffffffu, cnt, o);
        }
        if (n == 0)
            g_tpart[task] = make_float4(sq, spm, spp, cnt);
    }
}

__global__ void yolo_finalize_kernel(float* __restrict__ out) {
    const int tid  = threadIdx.x;
    const int lane = tid & 31;
    const int wid  = tid >> 5;

    __shared__ double dsh[3][8];
    __shared__ double tsh[4][6];   // sq, spm, spp, cnt per warp (warps 0..5)

    // ---- dense partials: per-scale sums ----
    double v0 = 0.0, v1 = 0.0, v2 = 0.0;
    for (int i = tid; i < NB0; i += 256) v0 += g_part[i];
    if (tid < NB1) v1 = g_part[NB0 + tid];
    if (tid < NB2) v2 = g_part[NB0 + NB1 + tid];
    #pragma unroll
    for (int o = 16; o > 0; o >>= 1) {
        v0 += __shfl_down_sync(0xffffffffu, v0, o);
        v1 += __shfl_down_sync(0xffffffffu, v1, o);
        v2 += __shfl_down_sync(0xffffffffu, v2, o);
    }
    if (lane == 0) { dsh[0][wid] = v0; dsh[1][wid] = v1; dsh[2][wid] = v2; }

    // ---- target partials: warp w handles tasks [w*32, w*32+32) ----
    if (wid < 6) {
        float4 tp = g_tpart[wid * 32 + lane];
        double a = tp.x, b = tp.y, c = tp.z, d = tp.w;
        #pragma unroll
        for (int o = 16; o > 0; o >>= 1) {
            a += __shfl_down_sync(0xffffffffu, a, o);
            b += __shfl_down_sync(0xffffffffu, b, o);
            c += __shfl_down_sync(0xffffffffu, c, o);
            d += __shfl_down_sync(0xffffffffu, d, o);
        }
        if (lane == 0) { tsh[0][wid] = a; tsh[1][wid] = b; tsh[2][wid] = c; tsh[3][wid] = d; }
    }
    __syncthreads();

    if (tid == 0) {
        double sall[3];
        #pragma unroll
        for (int s = 0; s < 3; s++) {
            double t = 0.0;
            #pragma unroll
            for (int w = 0; w < 8; w++) t += dsh[s][w];
            sall[s] = t;
        }
        const double cells[3] = {4915200.0, 1228800.0, 307200.0}; // B*A*H*W
        double loss = 0.0;
        #pragma unroll
        for (int s = 0; s < 3; s++) {
            double box = tsh[0][2 * s] + tsh[0][2 * s + 1];
            double pp  = tsh[1][2 * s] + tsh[1][2 * s + 1];
            double pn  = tsh[2][2 * s] + tsh[2][2 * s + 1];
            double np  = tsh[3][2 * s] + tsh[3][2 * s + 1];
            double nn  = cells[s] - np;
            loss += 0.05 * box / np + pp / np + (sall[s] - pn) / nn;
        }
        out[0] = (float)loss;
    }
}

extern "C" void kernel_launch(void* const* d_in, const int* in_sizes, int n_in,
                              void* d_out, int out_size) {
    (void)in_sizes; (void)n_in; (void)out_size;
    const float* pred0   = (const float*)d_in[0];
    const float* pred1   = (const float*)d_in[1];
    const float* pred2   = (const float*)d_in[2];
    const float* boxes   = (const float*)d_in[3];
    // d_in[4] = labels (unused, nc==1)
    const float* anchors = (const float*)d_in[5];
    float* out = (float*)d_out;

    yolo_main_kernel<<<TOTAL_BLOCKS, 256>>>(pred0, pred1, pred2, boxes, anchors);
    yolo_finalize_kernel<<<1, 256>>>(out);
}

// round 8
// speedup vs baseline: 1.0809x; 1.0265x over previous
#include <cuda_runtime.h>
#include <cuda_bf16.h>
#include <cstdint>

// ---------------------------------------------------------------------------
// YOLO loss (nc=1).  B=64, N=32, A=3, grids {160,80,40}, pred [B,18,G,G].
//
// loss = 0.05 * sum_s box_sq[s]/n_pos[s]
//      +        sum_s ( pos_plus[s]/n_pos[s] + (S_all[s]-pos_neg[s])/n_neg[s] )
//
// Single kernel, 648 blocks, NO source-level local arrays in hot paths
// (previous rounds spilled pointer/value arrays to local memory -> serialized
// LDL/STL, MLP_eff~1).  Dense work is plane-contiguous: pointer + immediate
// offsets only.
//   blocks [0,24):      192 warp-tasks (scale,batch) target matching
//   blocks [24,408):    s0, half obj-plane each (3200 f4)
//   blocks [408,600):   s1, one obj-plane each (1600 f4)
//   blocks [600,648):   s2, four obj-planes each (4 x 400 f4)
//   last block (ticket) reduces partials and writes the loss.
// ---------------------------------------------------------------------------

#define NN 32
#define TGT_BLOCKS 24
#define NB0D 384
#define NB1D 192
#define NB2D 48
#define DENSE_BLOCKS (NB0D + NB1D + NB2D)          // 624
#define TOTAL_BLOCKS (TGT_BLOCKS + DENSE_BLOCKS)   // 648

__device__ double   g_part[DENSE_BLOCKS];  // dense per-block partials
__device__ float4   g_tpart[192];          // target partials: sq, sp-, sp+, cnt
__device__ unsigned g_ticket;

__device__ __forceinline__ float sp(float x) {
    return fmaxf(x, 0.0f) + __logf(1.0f + __expf(-fabsf(x)));
}

struct Acc { float l0, l1, g0, g1; };

__device__ __forceinline__ void accum4(float4 v, Acc& a) {
    a.l0 += fmaxf(v.x, 0.0f) + fmaxf(v.y, 0.0f);
    a.l1 += fmaxf(v.z, 0.0f) + fmaxf(v.w, 0.0f);
    a.g0 += __log2f(1.0f + __expf(-fabsf(v.x))) + __log2f(1.0f + __expf(-fabsf(v.y)));
    a.g1 += __log2f(1.0f + __expf(-fabsf(v.z))) + __log2f(1.0f + __expf(-fabsf(v.w)));
}

// NF4 float4 elements starting at p (contiguous), 256 threads.
template <int NF4>
__device__ __forceinline__ void stream_sum(const float4* __restrict__ p,
                                           int tid, Acc& a) {
    constexpr int FULL = NF4 / 256;
    constexpr int TAIL = NF4 - FULL * 256;
    #pragma unroll
    for (int k = 0; k < FULL; k++) {
        float4 v = __ldg(p + k * 256 + tid);   // scalar per iter, imm offsets
        accum4(v, a);
    }
    if (TAIL > 0 && tid < TAIL) {
        float4 v = __ldg(p + FULL * 256 + tid);
        accum4(v, a);
    }
}

__global__ void __launch_bounds__(256, 2) yolo_kernel(
        const float* __restrict__ pred0,
        const float* __restrict__ pred1,
        const float* __restrict__ pred2,
        const float* __restrict__ boxes,
        const float* __restrict__ anchors,
        float* __restrict__ out) {
    const int bid  = blockIdx.x;
    const int tid  = threadIdx.x;
    const int lane = tid & 31;
    const int wid  = tid >> 5;

    __shared__ float  warpsum[8];
    __shared__ int    keys[8][NN];
    __shared__ double dsh[3][8];
    __shared__ bool   s_last;

    if (bid >= TGT_BLOCKS) {
        // ---------------- dense objectness pass (plane-contiguous) ----------------
        const int d = bid - TGT_BLOCKS;
        Acc a = {0.0f, 0.0f, 0.0f, 0.0f};
        if (d < NB0D) {
            // scale0: plane = 6400 f4 at offset plane*6*6400 + 4*6400; half = 3200 f4
            const float4* p = reinterpret_cast<const float4*>(pred0)
                            + (size_t)(d >> 1) * 38400 + 25600 + (size_t)(d & 1) * 3200;
            stream_sum<3200>(p, tid, a);
        } else if (d < NB0D + NB1D) {
            // scale1: one plane = 1600 f4 at plane*9600 + 6400
            const int pl = d - NB0D;
            const float4* p = reinterpret_cast<const float4*>(pred1)
                            + (size_t)pl * 9600 + 6400;
            stream_sum<1600>(p, tid, a);
        } else {
            // scale2: four planes of 400 f4 at plane*2400 + 1600
            const int p0 = (d - NB0D - NB1D) * 4;
            const float4* base = reinterpret_cast<const float4*>(pred2);
            stream_sum<400>(base + (size_t)(p0 + 0) * 2400 + 1600, tid, a);
            stream_sum<400>(base + (size_t)(p0 + 1) * 2400 + 1600, tid, a);
            stream_sum<400>(base + (size_t)(p0 + 2) * 2400 + 1600, tid, a);
            stream_sum<400>(base + (size_t)(p0 + 3) * 2400 + 1600, tid, a);
        }
        float v = (a.l0 + a.l1) + 0.69314718055994531f * (a.g0 + a.g1);

        #pragma unroll
        for (int o = 16; o > 0; o >>= 1)
            v += __shfl_down_sync(0xffffffffu, v, o);
        if (lane == 0) warpsum[wid] = v;
        __syncthreads();
        if (tid == 0) {
            double t = 0.0;
            #pragma unroll
            for (int w = 0; w < 8; w++) t += (double)warpsum[w];
            g_part[d] = t;
        }
    } else {
        // ---------------- sparse target pass: one (scale,batch) per warp ----------------
        const int task = bid * 8 + wid;          // 0..191
        const int s = task >> 6;
        const int b = task & 63;
        const int n = lane;

        const int G = (s == 0) ? 160 : (s == 1) ? 80 : 40;
        const float* pred = (s == 0) ? pred0 : (s == 1) ? pred1 : pred2;
        const int HW = G * G;

        float4 bx = reinterpret_cast<const float4*>(boxes)[b * NN + n];
        float gx = bx.x * (float)G;
        float gy = bx.y * (float)G;
        float gw = bx.z * (float)G;
        float gh = bx.w * (float)G;
        int gi = (int)gx;
        int gj = (int)gy;

        // anchor matching: argmax over a of prod(min(r,1/r)), first-max tiebreak
        float bestIou = -1.0f;
        float aw = 1.0f, ah = 1.0f;
        int best = 0;
        #pragma unroll
        for (int a = 0; a < 3; a++) {
            float Aw = anchors[s * 6 + a * 2 + 0];
            float Ah = anchors[s * 6 + a * 2 + 1];
            float rw = __fdiv_rn(Aw, gw);
            float rh = __fdiv_rn(Ah, gh);
            float iw = fminf(rw, __fdiv_rn(1.0f, rw));
            float ih = fminf(rh, __fdiv_rn(1.0f, rh));
            float iou = iw * ih;
            if (iou > bestIou) { bestIou = iou; best = a; aw = Aw; ah = Ah; }
        }

        // dedup: last write wins -> entry n live iff no later n' has same key
        int key = (best * G + gj) * G + gi;
        keys[wid][n] = key;
        __syncwarp();
        bool live = true;
        for (int m = n + 1; m < NN; m++)
            if (keys[wid][m] == key) { live = false; break; }

        float sq = 0.0f, spp = 0.0f, spm = 0.0f, cnt = 0.0f;
        if (live) {
            size_t base = (size_t)(b * 18 + best * 6) * HW + (size_t)gj * G + gi;
            float p0 = __ldg(pred + base);
            float p1 = __ldg(pred + base + (size_t)HW);
            float p2 = __ldg(pred + base + (size_t)2 * HW);
            float p3 = __ldg(pred + base + (size_t)3 * HW);
            float p4 = __ldg(pred + base + (size_t)4 * HW);

            float tx = gx - (float)gi;
            float ty = gy - (float)gj;
            float tw = logf(__fdiv_rn(gw, aw) + 1e-16f);
            float th = logf(__fdiv_rn(gh, ah) + 1e-16f);

            float d0 = p0 - tx, d1 = p1 - ty, d2 = p2 - tw, d3 = p3 - th;
            sq  = d0 * d0 + d1 * d1 + d2 * d2 + d3 * d3;
            spm = sp(-p4);
            spp = sp(p4);
            cnt = 1.0f;
        }

        #pragma unroll
        for (int o = 16; o > 0; o >>= 1) {
            sq  += __shfl_down_sync(0xffffffffu, sq,  o);
            spm += __shfl_down_sync(0xffffffffu, spm, o);
            spp += __shfl_down_sync(0xffffffffu, spp, o);
            cnt += __shfl_down_sync(0xffffffffu, cnt, o);
        }
        if (n == 0)
            g_tpart[task] = make_float4(sq, spm, spp, cnt);
    }

    // ---------------- last-block finalize ----------------
    __syncthreads();                 // all block stores done
    if (tid == 0) {
        __threadfence();             // publish this block's results
        unsigned t = atomicAdd(&g_ticket, 1u);
        s_last = (t == TOTAL_BLOCKS - 1);
    }
    __syncthreads();
    if (s_last) {
        __threadfence();
        // dense partials per scale
        double v0 = 0.0, v1 = 0.0, v2 = 0.0;
        v0 = ((volatile double*)g_part)[tid];
        if (tid < NB0D - 256) v0 += ((volatile double*)g_part)[256 + tid];
        if (tid < NB1D) v1 = ((volatile double*)g_part)[NB0D + tid];
        if (tid < NB2D) v2 = ((volatile double*)g_part)[NB0D + NB1D + tid];
        #pragma unroll
        for (int o = 16; o > 0; o >>= 1) {
            v0 += __shfl_down_sync(0xffffffffu, v0, o);
            v1 += __shfl_down_sync(0xffffffffu, v1, o);
            v2 += __shfl_down_sync(0xffffffffu, v2, o);
        }
        if (lane == 0) { dsh[0][wid] = v0; dsh[1][wid] = v1; dsh[2][wid] = v2; }

        // target partials: warp w sums tasks [w*32, w*32+32)
        __shared__ double tsh[4][6];
        if (wid < 6) {
            const volatile float* tp = (const volatile float*)g_tpart;
            int o4 = (wid * 32 + lane) * 4;
            double a  = (double)tp[o4 + 0];
            double b  = (double)tp[o4 + 1];
            double c  = (double)tp[o4 + 2];
            double dd = (double)tp[o4 + 3];
            #pragma unroll
            for (int o = 16; o > 0; o >>= 1) {
                a  += __shfl_down_sync(0xffffffffu, a,  o);
                b  += __shfl_down_sync(0xffffffffu, b,  o);
                c  += __shfl_down_sync(0xffffffffu, c,  o);
                dd += __shfl_down_sync(0xffffffffu, dd, o);
            }
            if (lane == 0) { tsh[0][wid] = a; tsh[1][wid] = b; tsh[2][wid] = c; tsh[3][wid] = dd; }
        }
        __syncthreads();

        if (tid == 0) {
            double sall0 = 0.0, sall1 = 0.0, sall2 = 0.0;
            #pragma unroll
            for (int w = 0; w < 8; w++) {
                sall0 += dsh[0][w]; sall1 += dsh[1][w]; sall2 += dsh[2][w];
            }
            const double cells[3] = {4915200.0, 1228800.0, 307200.0};
            double sall[3] = {sall0, sall1, sall2};
            double loss = 0.0;
            #pragma unroll
            for (int s = 0; s < 3; s++) {
                double box = tsh[0][2 * s] + tsh[0][2 * s + 1];
                double pp  = tsh[1][2 * s] + tsh[1][2 * s + 1];
                double pn  = tsh[2][2 * s] + tsh[2][2 * s + 1];
                double np  = tsh[3][2 * s] + tsh[3][2 * s + 1];
                double nn  = cells[s] - np;
                loss += 0.05 * box / np + pp / np + (sall[s] - pn) / nn;
            }
            g_ticket = 0u;           // reset for next replay
            out[0] = (float)loss;
        }
    }
}

extern "C" void kernel_launch(void* const* d_in, const int* in_sizes, int n_in,
                              void* d_out, int out_size) {
    (void)in_sizes; (void)n_in; (void)out_size;
    const float* pred0   = (const float*)d_in[0];
    const float* pred1   = (const float*)d_in[1];
    const float* pred2   = (const float*)d_in[2];
    const float* boxes   = (const float*)d_in[3];
    // d_in[4] = labels (unused, nc==1)
    const float* anchors = (const float*)d_in[5];
    float* out = (float*)d_out;

    yolo_kernel<<<TOTAL_BLOCKS, 256>>>(pred0, pred1, pred2, boxes, anchors, out);
}